// round 12
// baseline (speedup 1.0000x reference)
#include <cuda_runtime.h>

#define NEG (-1e30f)

// dims
#define BB   8
#define NN   196
#define DD   128
#define DFF  256
#define PD   256
#define MM   (BB*NN)   // 1568
#define CC   1000

// -------- scratch (device globals; no allocation allowed) --------
__device__ __align__(128) float g_h[MM * DD];
__device__ __align__(128) float g_q[MM * DD];   // also ff2's u scratch
__device__ __align__(128) float g_k[MM * DD];
__device__ __align__(128) float g_v[MM * DD];
__device__ __align__(128) float g_t[MM * DFF];
__device__ __align__(128) float g_mx2[MM * 2];  // per-row max, 2 column-halves

// -------- Blackwell packed helpers --------
__device__ __forceinline__ float fmax3(float a, float b, float c) {
    float d;
    asm("max.f32 %0, %1, %2, %3;" : "=f"(d) : "f"(a), "f"(b), "f"(c));
    return d;
}
__device__ __forceinline__ unsigned long long addx2(unsigned long long a,
                                                    unsigned long long b) {
    unsigned long long r;
    asm("add.rn.f32x2 %0, %1, %2;" : "=l"(r) : "l"(a), "l"(b));
    return r;
}
__device__ __forceinline__ void unpk(float& lo, float& hi, unsigned long long v) {
    asm("mov.b64 {%0, %1}, %2;" : "=f"(lo), "=f"(hi) : "l"(v));
}
__device__ __forceinline__ unsigned long long pk(float lo, float hi) {
    unsigned long long v;
    asm("mov.b64 %0, {%1, %2};" : "=l"(v) : "f"(lo), "f"(hi));
    return v;
}

// -------- cp.async helpers --------
__device__ __forceinline__ void cpa16(float* dst, const float* src) {
    unsigned a = (unsigned)__cvta_generic_to_shared(dst);
    asm volatile("cp.async.cg.shared.global [%0], [%1], 16;" :: "r"(a), "l"(src));
}
__device__ __forceinline__ void cpa_commit() {
    asm volatile("cp.async.commit_group;");
}
template<int N>
__device__ __forceinline__ void cpa_wait() {
    asm volatile("cp.async.wait_group %0;" :: "n"(N));
}

// ---------------------------------------------------------------
// X source providers (gmem addr of a 16B piece of tile row `row`)
// ---------------------------------------------------------------
template<int K>
struct XRowT {
    const float* X; int m0;
    __device__ __forceinline__ const float* src(int row, int kp) const {
        return &X[(m0 + row) * K + kp];
    }
};
// patchify-on-the-fly: x is (8,224,224)
struct XPatch {
    const float* x; int m0;
    __device__ __forceinline__ const float* src(int row, int kp) const {
        int m = m0 + row;
        int b = m / NN, n = m % NN;
        int gy = n / 14, gx = n % 14;
        int py = kp >> 4, px = kp & 15;    // px in {0,4,8,12}
        return &x[(b * 224 + gy * 16 + py) * 224 + gx * 16 + px];
    }
};

// ---------------------------------------------------------------
// W-in-registers tropical GEMM core.
// Block 256 thr = 64 cols (c=t&63) x 4 K-groups (g=t>>6, Kq=K/4 each).
// Output tile 8 rows x 64 cols (this block's col-set).
// sw: 64 x (K+4) staging (pad 4: strided W->reg LDS conflict-free)
// sx: 8 x K (broadcast reads only; no pad needed)
// ---------------------------------------------------------------
template<int K, class XL>
__device__ __forceinline__ void trop_core(const XL& xl, const float* __restrict__ Wb,
                                          float acc[8], float* sw, float* sx,
                                          ulonglong2* w2 /* K/16 entries */)
{
    constexpr int KQ = K / 4;     // K per group
    constexpr int PPR = K / 4;    // 16B pieces per row
    constexpr int LDW = K + 4;
    int t = threadIdx.x;
    int c = t & 63, g = t >> 6;

    // stage W (64 rows x K floats), coalesced
#pragma unroll
    for (int p = 0; p < K / 16; p++) {
        int l = p * 256 + t;
        int row = l / PPR, kp = (l % PPR) * 4;
        cpa16(&sw[row * LDW + kp], &Wb[row * K + kp]);
    }
    // stage X (8 rows x K floats)
#pragma unroll
    for (int p = 0; p < (8 * PPR) / 256; p++) {
        int l = p * 256 + t;
        int row = l / PPR, kp = (l % PPR) * 4;
        cpa16(&sx[row * K + kp], xl.src(row, kp));
    }
    cpa_commit();
    cpa_wait<0>();
    __syncthreads();

    // W -> registers (this thread's column, its K-quarter)
#pragma unroll
    for (int j = 0; j < K / 16; j++)
        w2[j] = *(const ulonglong2*)&sw[c * LDW + g * KQ + j * 4];

    // compute: per m, stream the X row-quarter (broadcast LDS) against regs
#pragma unroll
    for (int m = 0; m < 8; m++) {
        float a = NEG;
        const float* xr = &sx[m * K + g * KQ];
#pragma unroll
        for (int j = 0; j < K / 16; j++) {
            ulonglong2 xv = *(const ulonglong2*)&xr[j * 4];
            float s0, s1, s2, s3;
            unpk(s0, s1, addx2(xv.x, w2[j].x));
            unpk(s2, s3, addx2(xv.y, w2[j].y));
            a = fmax3(a, s0, s1);
            a = fmax3(a, s2, s3);
        }
        acc[m] = a;
    }
}

// combine 4 K-groups; afterwards group 0 (t<64) holds the result
__device__ __forceinline__ void combine4(float acc[8], float* sc) {
    int t = threadIdx.x, c = t & 63, g = t >> 6;
    if (g > 0) {
#pragma unroll
        for (int m = 0; m < 8; m++) sc[((g - 1) * 8 + m) * 64 + c] = acc[m];
    }
    __syncthreads();
    if (g == 0) {
#pragma unroll
        for (int m = 0; m < 8; m++) {
            acc[m] = fmax3(acc[m], sc[m * 64 + c], sc[(8 + m) * 64 + c]);
            acc[m] = fmaxf(acc[m], sc[(16 + m) * 64 + c]);
        }
    }
}

#define DSMEM(K) ((64 * ((K) + 4) + 8 * (K) + 3 * 8 * 64) * 4)

__device__ __forceinline__ float mxv(int m) {
    return fmaxf(g_mx2[2 * m], g_mx2[2 * m + 1]);
}

// ---------------------------------------------------------------
// embed: h = trop_mm(patchify(x), embed_W) + pos ; partial rowmax
// grid (196, 2 colsets), block 256
// ---------------------------------------------------------------
__global__ void __launch_bounds__(256) embed_kernel(
        const float* __restrict__ x, const float* __restrict__ W,
        const float* __restrict__ pos) {
    extern __shared__ float dyn[];
    float* sw = dyn;
    float* sx = dyn + 64 * 260;
    float* sc = sx + 8 * 256;
    __shared__ float red[2][8];
    int t = threadIdx.x, m0 = blockIdx.x * 8, cs = blockIdx.y;
    float acc[8];
    ulonglong2 w2[16];
    XPatch xl{x, m0};
    trop_core<256>(xl, W + cs * 64 * PD, acc, sw, sx, w2);
    combine4(acc, sc);
    int c = t & 63, g = t >> 6;
    if (g == 0) {
        int lane = t & 31, w = t >> 5;
#pragma unroll
        for (int m = 0; m < 8; m++) {
            float a = acc[m] + pos[((m0 + m) % NN) * DD + cs * 64 + c];
            g_h[(m0 + m) * DD + cs * 64 + c] = a;
            float v = a;
#pragma unroll
            for (int o = 16; o; o >>= 1) v = fmaxf(v, __shfl_xor_sync(~0u, v, o));
            if (lane == 0) red[w][m] = v;
        }
    }
    __syncthreads();
    if (t < 8) g_mx2[(m0 + t) * 2 + cs] = fmaxf(red[0][t], red[1][t]);
}

// ---------------------------------------------------------------
// qkv: O = trop_mm(h, W) - mx ; grid (196, 2 colsets, 3 weights)
// ---------------------------------------------------------------
__global__ void __launch_bounds__(256) qkv_kernel(
        const float* __restrict__ qW, const float* __restrict__ kW,
        const float* __restrict__ vW) {
    extern __shared__ float dyn[];
    float* sw = dyn;
    float* sx = dyn + 64 * 132;
    float* sc = sx + 8 * 128;
    int t = threadIdx.x, m0 = blockIdx.x * 8, cs = blockIdx.y;
    const float* W = (blockIdx.z == 0) ? qW : (blockIdx.z == 1) ? kW : vW;
    float* O = (blockIdx.z == 0) ? g_q : (blockIdx.z == 1) ? g_k : g_v;
    float acc[8];
    ulonglong2 w2[8];
    XRowT<DD> xl{g_h, m0};
    trop_core<128>(xl, W + cs * 64 * DD, acc, sw, sx, w2);
    combine4(acc, sc);
    int c = t & 63, g = t >> 6;
    if (g == 0) {
#pragma unroll
        for (int m = 0; m < 8; m++)
            O[(m0 + m) * DD + cs * 64 + c] = acc[m] - mxv(m0 + m);
    }
}

// ---------------------------------------------------------------
// fused attention + residual + rowmax
// grid (25, 8), block 256 = 8 i-rows x 32 lanes (4 d each)
// ---------------------------------------------------------------
__global__ void attn_kernel() {
    __shared__ float ks[8][128];
    __shared__ float vs[8][128];
    int t = threadIdx.x;
    int b = blockIdx.y;
    int il = t >> 5, lane = t & 31;
    int d0 = lane * 4;
    int i = blockIdx.x * 8 + il;
    bool iv = (i < NN);

    const float* qp = g_q + (b * NN + (iv ? i : 0)) * DD + d0;
    float q0 = iv ? qp[0] : NEG, q1 = iv ? qp[1] : NEG;
    float q2 = iv ? qp[2] : NEG, q3 = iv ? qp[3] : NEG;
    unsigned long long Q01 = pk(q0, q1), Q23 = pk(q2, q3);
    float U0 = NEG, U1 = NEG, U2 = NEG, U3 = NEG;

    for (int j0 = 0; j0 < NN; j0 += 8) {
        int j = j0 + il;
        if (j < NN) {
            const float* kp_ = g_k + (b * NN + j) * DD + d0;
            const float* vp_ = g_v + (b * NN + j) * DD + d0;
            *(float4*)&ks[il][d0] = *(const float4*)&kp_[0];
            *(float4*)&vs[il][d0] = *(const float4*)&vp_[0];
        } else {
            float4 nv = make_float4(NEG, NEG, NEG, NEG);
            *(float4*)&ks[il][d0] = nv;
            *(float4*)&vs[il][d0] = nv;
        }
        __syncthreads();
#pragma unroll
        for (int jj = 0; jj < 8; jj++) {
            ulonglong2 kv = *(const ulonglong2*)&ks[jj][d0];
            float s0, s1, s2, s3;
            unpk(s0, s1, addx2(Q01, kv.x));
            unpk(s2, s3, addx2(Q23, kv.y));
            float s = fmaxf(fmax3(s0, s1, s2), s3);
#pragma unroll
            for (int o = 16; o; o >>= 1) s = fmaxf(s, __shfl_xor_sync(~0u, s, o));
            ulonglong2 vv = *(const ulonglong2*)&vs[jj][d0];
            unsigned long long S2 = pk(s, s);
            float a0, a1, a2, a3;
            unpk(a0, a1, addx2(S2, vv.x));
            unpk(a2, a3, addx2(S2, vv.y));
            U0 = fmaxf(U0, a0); U1 = fmaxf(U1, a1);
            U2 = fmaxf(U2, a2); U3 = fmaxf(U3, a3);
        }
        __syncthreads();
    }

    float um = fmax3(fmaxf(U0, U1), U2, U3);
#pragma unroll
    for (int o = 16; o; o >>= 1) um = fmaxf(um, __shfl_xor_sync(~0u, um, o));

    if (iv) {
        float* hp = g_h + (b * NN + i) * DD + d0;
        float h0 = fmaxf(hp[0], U0 - um), h1 = fmaxf(hp[1], U1 - um);
        float h2 = fmaxf(hp[2], U2 - um), h3 = fmaxf(hp[3], U3 - um);
        hp[0] = h0; hp[1] = h1; hp[2] = h2; hp[3] = h3;
        float v = fmax3(fmaxf(h0, h1), h2, h3);
#pragma unroll
        for (int o = 16; o; o >>= 1) v = fmaxf(v, __shfl_xor_sync(~0u, v, o));
        if (lane == 0) {
            int m = b * NN + i;
            g_mx2[2 * m] = v;
            g_mx2[2 * m + 1] = v;
        }
    }
}

// ---------------------------------------------------------------
// ff1: t = max(trop_mm(h, f1W) - mx, tau) ; grid (196, 4 colsets)
// ---------------------------------------------------------------
__global__ void __launch_bounds__(256) ff1_kernel(
        const float* __restrict__ W, const float* __restrict__ tau) {
    extern __shared__ float dyn[];
    float* sw = dyn;
    float* sx = dyn + 64 * 132;
    float* sc = sx + 8 * 128;
    int t = threadIdx.x, m0 = blockIdx.x * 8, cs = blockIdx.y;
    float acc[8];
    ulonglong2 w2[8];
    XRowT<DD> xl{g_h, m0};
    trop_core<128>(xl, W + cs * 64 * DD, acc, sw, sx, w2);
    combine4(acc, sc);
    int c = t & 63, g = t >> 6;
    if (g == 0) {
        float tv = tau[0];
#pragma unroll
        for (int m = 0; m < 8; m++)
            g_t[(m0 + m) * DFF + cs * 64 + c] =
                fmaxf(acc[m] - mxv(m0 + m), tv);
    }
}

// ---------------------------------------------------------------
// ff2mm: u = trop_mm(t, f2W) -> g_q scratch ; grid (196, 2 colsets)
// ---------------------------------------------------------------
__global__ void __launch_bounds__(256) ff2mm_kernel(const float* __restrict__ W) {
    extern __shared__ float dyn[];
    float* sw = dyn;
    float* sx = dyn + 64 * 260;
    float* sc = sx + 8 * 256;
    int t = threadIdx.x, m0 = blockIdx.x * 8, cs = blockIdx.y;
    float acc[8];
    ulonglong2 w2[16];
    XRowT<DFF> xl{g_t, m0};
    trop_core<256>(xl, W + cs * 64 * DFF, acc, sw, sx, w2);
    combine4(acc, sc);
    int c = t & 63, g = t >> 6;
    if (g == 0) {
#pragma unroll
        for (int m = 0; m < 8; m++)
            g_q[(m0 + m) * DD + cs * 64 + c] = acc[m];
    }
}

// ---------------------------------------------------------------
// ff2ep: h = max(h, u - rowmax(u)); g_mx2 = rowmax(h)
// grid 196, block 128 (8 rows/block)
// ---------------------------------------------------------------
__global__ void ff2ep_kernel() {
    __shared__ float red[4][8];
    int t = threadIdx.x, m0 = blockIdx.x * 8;
    int lane = t & 31, w = t >> 5;
    float u[8], hn[8];
#pragma unroll
    for (int m = 0; m < 8; m++) {
        u[m] = g_q[(m0 + m) * DD + t];
        float v = u[m];
#pragma unroll
        for (int o = 16; o; o >>= 1) v = fmaxf(v, __shfl_xor_sync(~0u, v, o));
        if (lane == 0) red[w][m] = v;
    }
    __syncthreads();
#pragma unroll
    for (int m = 0; m < 8; m++) {
        float rm = fmax3(fmaxf(red[0][m], red[1][m]), red[2][m], red[3][m]);
        hn[m] = fmaxf(g_h[(m0 + m) * DD + t], u[m] - rm);
        g_h[(m0 + m) * DD + t] = hn[m];
    }
    __syncthreads();
#pragma unroll
    for (int m = 0; m < 8; m++) {
        float v = hn[m];
#pragma unroll
        for (int o = 16; o; o >>= 1) v = fmaxf(v, __shfl_xor_sync(~0u, v, o));
        if (lane == 0) red[w][m] = v;
    }
    __syncthreads();
    if (t < 8) {
        float v = fmax3(fmaxf(red[0][t], red[1][t]), red[2][t], red[3][t]);
        g_mx2[(m0 + t) * 2] = v;
        g_mx2[(m0 + t) * 2 + 1] = v;
    }
}

// ---------------------------------------------------------------
// head with fused tropical global pool
// grid (8, 63), block 128
// ---------------------------------------------------------------
__global__ void head_kernel(const float* __restrict__ W, const float* __restrict__ ls,
                            float* __restrict__ out) {
    __shared__ float sp[128];
    int t = threadIdx.x, b = blockIdx.x;
    const float* hp = g_h + b * NN * DD + t;
    float v0 = NEG, v1 = NEG, v2 = NEG, v3 = NEG;
    for (int n = 0; n < NN; n += 4) {
        v0 = fmaxf(v0, hp[n * DD]);
        v1 = fmaxf(v1, hp[(n + 1) * DD]);
        v2 = fmaxf(v2, hp[(n + 2) * DD]);
        v3 = fmaxf(v3, hp[(n + 3) * DD]);
    }
    sp[t] = fmax3(fmaxf(v0, v1), v2, v3);
    __syncthreads();

    int c = blockIdx.y * 16 + (t >> 3);
    int dp = (t & 7) * 16;
    float acc = NEG;
    if (c < CC) {
        const float* w = W + c * DD + dp;
#pragma unroll
        for (int d = 0; d < 16; d += 4) {
            float4 wv = *(const float4*)&w[d];
            acc = fmax3(acc, fmaxf(sp[dp + d] + wv.x, sp[dp + d + 1] + wv.y),
                        fmaxf(sp[dp + d + 2] + wv.z, sp[dp + d + 3] + wv.w));
        }
    }
#pragma unroll
    for (int o = 4; o; o >>= 1) acc = fmaxf(acc, __shfl_xor_sync(~0u, acc, o));
    if ((t & 7) == 0 && c < CC) out[b * CC + c] = acc * ls[0];
}

// ---------------------------------------------------------------
extern "C" void kernel_launch(void* const* d_in, const int* in_sizes, int n_in,
                              void* d_out, int out_size) {
    const float* x      = (const float*)d_in[0];
    const float* embedW = (const float*)d_in[1];
    const float* pos    = (const float*)d_in[2];
    const float* qW[2]  = {(const float*)d_in[3],  (const float*)d_in[9]};
    const float* kW[2]  = {(const float*)d_in[4],  (const float*)d_in[10]};
    const float* vW[2]  = {(const float*)d_in[5],  (const float*)d_in[11]};
    const float* f1W[2] = {(const float*)d_in[6],  (const float*)d_in[12]};
    const float* f2W[2] = {(const float*)d_in[7],  (const float*)d_in[13]};
    const float* tau[2] = {(const float*)d_in[8],  (const float*)d_in[14]};
    const float* headW  = (const float*)d_in[15];
    const float* ls     = (const float*)d_in[16];
    float* out = (float*)d_out;

    cudaFuncSetAttribute(embed_kernel, cudaFuncAttributeMaxDynamicSharedMemorySize, DSMEM(256));
    cudaFuncSetAttribute(ff2mm_kernel, cudaFuncAttributeMaxDynamicSharedMemorySize, DSMEM(256));

    embed_kernel<<<dim3(196, 2), 256, DSMEM(256)>>>(x, embedW, pos);

    for (int l = 0; l < 2; l++) {
        qkv_kernel<<<dim3(196, 2, 3), 256, DSMEM(128)>>>(qW[l], kW[l], vW[l]);
        attn_kernel<<<dim3(25, BB), 256>>>();
        ff1_kernel<<<dim3(196, 4), 256, DSMEM(128)>>>(f1W[l], tau[l]);
        ff2mm_kernel<<<dim3(196, 2), 256, DSMEM(256)>>>(f2W[l]);
        ff2ep_kernel<<<196, 128>>>();
    }

    head_kernel<<<dim3(BB, 63), 128>>>(headW, ls, out);
}

// round 14
// speedup vs baseline: 1.0940x; 1.0940x over previous
#include <cuda_runtime.h>

#define NEG (-1e30f)

// dims
#define BB   8
#define NN   196
#define DD   128
#define DFF  256
#define PD   256
#define MM   (BB*NN)   // 1568
#define CC   1000

// -------- scratch (device globals; no allocation allowed) --------
__device__ __align__(128) float g_h[MM * DD];
__device__ __align__(128) float g_q[MM * DD];   // also ff2's u scratch
__device__ __align__(128) float g_k[MM * DD];
__device__ __align__(128) float g_v[MM * DD];
__device__ __align__(128) float g_t[MM * DFF];
__device__ __align__(128) float g_mx2[MM * 2];  // per-row max, 2 column-halves

// -------- Blackwell packed helpers --------
__device__ __forceinline__ float fmax3(float a, float b, float c) {
    float d;
    asm("max.f32 %0, %1, %2, %3;" : "=f"(d) : "f"(a), "f"(b), "f"(c));
    return d;
}
__device__ __forceinline__ unsigned long long addx2(unsigned long long a,
                                                    unsigned long long b) {
    unsigned long long r;
    asm("add.rn.f32x2 %0, %1, %2;" : "=l"(r) : "l"(a), "l"(b));
    return r;
}
__device__ __forceinline__ void unpk(float& lo, float& hi, unsigned long long v) {
    asm("mov.b64 {%0, %1}, %2;" : "=f"(lo), "=f"(hi) : "l"(v));
}
__device__ __forceinline__ unsigned long long pk(float lo, float hi) {
    unsigned long long v;
    asm("mov.b64 %0, {%1, %2};" : "=l"(v) : "f"(lo), "f"(hi));
    return v;
}

// -------- cp.async helpers --------
__device__ __forceinline__ void cpa16(float* dst, const float* src) {
    unsigned a = (unsigned)__cvta_generic_to_shared(dst);
    asm volatile("cp.async.cg.shared.global [%0], [%1], 16;" :: "r"(a), "l"(src));
}
__device__ __forceinline__ void cpa_commit() {
    asm volatile("cp.async.commit_group;");
}
template<int N>
__device__ __forceinline__ void cpa_wait() {
    asm volatile("cp.async.wait_group %0;" :: "n"(N));
}

// ---------------------------------------------------------------
// X source providers: gmem addr of a 16B piece of (tile, row)
// ---------------------------------------------------------------
template<int K>
struct XRowT {
    const float* X; int m0; int tstride;
    __device__ __forceinline__ const float* src(int tile, int row, int kp) const {
        return &X[(m0 + tile * tstride + row) * K + kp];
    }
};
// patchify-on-the-fly: x is (8,224,224)
struct XPatch {
    const float* x; int m0;
    __device__ __forceinline__ const float* src(int, int row, int kp) const {
        int m = m0 + row;
        int b = m / NN, n = m % NN;
        int gy = n / 14, gx = n % 14;
        int py = kp >> 4, px = kp & 15;    // px in {0,4,8,12}
        return &x[(b * 224 + gy * 16 + py) * 224 + gx * 16 + px];
    }
};

// ---------------------------------------------------------------
// W-in-registers multi-tile tropical GEMM driver.
// Block 256 thr = 64 cols (c=t&63) x 4 K-groups (g=t>>6).
// W staged ONCE (in 128-col chunks through a 64x132 buffer) -> regs.
// NT row-tiles of 8 rows; X for tile1 prefetched during tile0 compute.
// dyn: sw[64*132], sx[NT][8*K], sc[24*64]   (= 48128 B for all configs)
// epi(tile, acc[8], c) runs on g==0 threads (t<64).
// ---------------------------------------------------------------
template<int K, int NT, class XL, class EPI>
__device__ __forceinline__ void trop_drive(const XL& xl, const float* __restrict__ Wb,
                                           float* dyn, const EPI& epi)
{
    constexpr int LDW = 132;
    constexpr int KQ = K / 4;
    float* sw = dyn;
    float* sx = sw + 64 * LDW;
    float* sc = sx + NT * 8 * K;
    int t = threadIdx.x, c = t & 63, g = t >> 6;
    ulonglong2 w2[KQ / 4];

    // stage X tile 0 (8 rows x K floats; K/4*8 pieces over 256 thr)
#pragma unroll
    for (int p = 0; p < (8 * K / 4) / 256; p++) {
        int l = p * 256 + t;
        int row = l / (K / 4), kp = (l % (K / 4)) * 4;
        cpa16(&sx[row * K + kp], xl.src(0, row, kp));
    }
    cpa_commit();

    // stage W in 128-col chunks, load this thread's K-quarter to regs
#pragma unroll
    for (int kc = 0; kc < K / 128; kc++) {
#pragma unroll
        for (int p = 0; p < 8; p++) {        // 64 rows x 32 pieces / 256 thr
            int l = p * 256 + t;
            int row = l >> 5, kp = (l & 31) * 4;
            cpa16(&sw[row * LDW + kp], &Wb[row * K + kc * 128 + kp]);
        }
        cpa_commit();
        cpa_wait<0>();
        __syncthreads();
        if (K == 128) {
#pragma unroll
            for (int j = 0; j < KQ / 4; j++)
                w2[j] = *(const ulonglong2*)&sw[c * LDW + g * KQ + j * 4];
        } else {     // K==256: chunk kc holds quarters of groups 2kc, 2kc+1
            if ((g >> 1) == kc) {
#pragma unroll
                for (int j = 0; j < KQ / 4; j++)
                    w2[j] = *(const ulonglong2*)&sw[c * LDW + (g & 1) * 64 + j * 4];
            }
            __syncthreads();                 // before chunk overwrite
        }
    }

    // prefetch X tile 1
    if (NT > 1) {
#pragma unroll
        for (int p = 0; p < (8 * K / 4) / 256; p++) {
            int l = p * 256 + t;
            int row = l / (K / 4), kp = (l % (K / 4)) * 4;
            cpa16(&sx[8 * K + row * K + kp], xl.src(1, row, kp));
        }
        cpa_commit();
    }

#pragma unroll
    for (int tile = 0; tile < NT; tile++) {
        if (tile > 0) { cpa_wait<0>(); __syncthreads(); }
        float acc[8];
#pragma unroll
        for (int m = 0; m < 8; m++) {
            float a = NEG;
            const float* xr = &sx[tile * 8 * K + m * K + g * KQ];
#pragma unroll
            for (int j = 0; j < KQ / 4; j++) {
                ulonglong2 xv = *(const ulonglong2*)&xr[j * 4];   // broadcast LDS
                float s0, s1, s2, s3;
                unpk(s0, s1, addx2(xv.x, w2[j].x));
                unpk(s2, s3, addx2(xv.y, w2[j].y));
                a = fmax3(a, s0, s1);
                a = fmax3(a, s2, s3);
            }
            acc[m] = a;
        }
        if (g > 0) {
#pragma unroll
            for (int m = 0; m < 8; m++) sc[((g - 1) * 8 + m) * 64 + c] = acc[m];
        }
        __syncthreads();
        if (g == 0) {
#pragma unroll
            for (int m = 0; m < 8; m++) {
                acc[m] = fmax3(acc[m], sc[m * 64 + c], sc[(8 + m) * 64 + c]);
                acc[m] = fmaxf(acc[m], sc[(16 + m) * 64 + c]);
            }
            epi(tile, acc, c);
        }
    }
}

#define DSMEM ((64 * 132 + 2 * 8 * 256 + 24 * 64) * 4)   // 48128 B, max config

__device__ __forceinline__ float mxv(int m) {
    return fmaxf(g_mx2[2 * m], g_mx2[2 * m + 1]);
}

// ---------------------------------------------------------------
// embed: h = trop_mm(patchify(x), embed_W) + pos ; partial rowmax
// grid (196, 2 colsets), block 256, NT=1, K=256
// ---------------------------------------------------------------
__global__ void __launch_bounds__(256) embed_kernel(
        const float* __restrict__ x, const float* __restrict__ W,
        const float* __restrict__ pos) {
    extern __shared__ float dyn[];
    __shared__ float red[2][8];
    int t = threadIdx.x, m0 = blockIdx.x * 8, cs = blockIdx.y;
    XPatch xl{x, m0};
    trop_drive<256, 1>(xl, W + cs * 64 * PD, dyn,
        [&](int, float* acc, int c) {
            int lane = c & 31, w = c >> 5;
#pragma unroll
            for (int m = 0; m < 8; m++) {
                float a = acc[m] + pos[((m0 + m) % NN) * DD + cs * 64 + c];
                g_h[(m0 + m) * DD + cs * 64 + c] = a;
                float v = a;
#pragma unroll
                for (int o = 16; o; o >>= 1) v = fmaxf(v, __shfl_xor_sync(~0u, v, o));
                if (lane == 0) red[w][m] = v;
            }
        });
    __syncthreads();
    if (t < 8) g_mx2[(m0 + t) * 2 + cs] = fmaxf(red[0][t], red[1][t]);
}

// ---------------------------------------------------------------
// qkv: O = trop_mm(h, W) - mx ; grid (98, 2 colsets, 3 weights), NT=2
// ---------------------------------------------------------------
__global__ void __launch_bounds__(256) qkv_kernel(
        const float* __restrict__ qW, const float* __restrict__ kW,
        const float* __restrict__ vW) {
    extern __shared__ float dyn[];
    int m0 = blockIdx.x * 8, cs = blockIdx.y;
    const float* W = (blockIdx.z == 0) ? qW : (blockIdx.z == 1) ? kW : vW;
    float* O = (blockIdx.z == 0) ? g_q : (blockIdx.z == 1) ? g_k : g_v;
    XRowT<DD> xl{g_h, m0, 784};
    trop_drive<128, 2>(xl, W + cs * 64 * DD, dyn,
        [&](int tile, float* acc, int c) {
            int mb = m0 + tile * 784;
#pragma unroll
            for (int m = 0; m < 8; m++)
                O[(mb + m) * DD + cs * 64 + c] = acc[m] - mxv(mb + m);
        });
}

// ---------------------------------------------------------------
// fused attention + residual + rowmax
// grid (49, 8), block 128 = 4 i-rows x 32 lanes (4 d each); 196 = 49*4
// ---------------------------------------------------------------
__global__ void attn_kernel() {
    __shared__ float ks[8][128];
    __shared__ float vs[8][128];
    int t = threadIdx.x;
    int b = blockIdx.y;
    int il = t >> 5, lane = t & 31;
    int d0 = lane * 4;
    int i = blockIdx.x * 4 + il;          // always < 196

    const float* qp = g_q + (b * NN + i) * DD + d0;
    unsigned long long Q01 = pk(qp[0], qp[1]), Q23 = pk(qp[2], qp[3]);
    float U0 = NEG, U1 = NEG, U2 = NEG, U3 = NEG;

    int jl = t >> 4, ld = (t & 15) * 8;   // staging role: 8 j-rows x 16 lanes
    for (int j0 = 0; j0 < NN; j0 += 8) {
        int j = j0 + jl;
        if (j < NN) {
            const float* kp_ = g_k + (b * NN + j) * DD + ld;
            const float* vp_ = g_v + (b * NN + j) * DD + ld;
            *(float4*)&ks[jl][ld]     = *(const float4*)&kp_[0];
            *(float4*)&ks[jl][ld + 4] = *(const float4*)&kp_[4];
            *(float4*)&vs[jl][ld]     = *(const float4*)&vp_[0];
            *(float4*)&vs[jl][ld + 4] = *(const float4*)&vp_[4];
        } else {
            float4 nv = make_float4(NEG, NEG, NEG, NEG);
            *(float4*)&ks[jl][ld] = nv; *(float4*)&ks[jl][ld + 4] = nv;
            *(float4*)&vs[jl][ld] = nv; *(float4*)&vs[jl][ld + 4] = nv;
        }
        __syncthreads();
#pragma unroll
        for (int jj = 0; jj < 8; jj++) {
            ulonglong2 kv = *(const ulonglong2*)&ks[jj][d0];
            float s0, s1, s2, s3;
            unpk(s0, s1, addx2(Q01, kv.x));
            unpk(s2, s3, addx2(Q23, kv.y));
            float s = fmaxf(fmax3(s0, s1, s2), s3);
#pragma unroll
            for (int o = 16; o; o >>= 1) s = fmaxf(s, __shfl_xor_sync(~0u, s, o));
            ulonglong2 vv = *(const ulonglong2*)&vs[jj][d0];
            unsigned long long S2 = pk(s, s);
            float a0, a1, a2, a3;
            unpk(a0, a1, addx2(S2, vv.x));
            unpk(a2, a3, addx2(S2, vv.y));
            U0 = fmaxf(U0, a0); U1 = fmaxf(U1, a1);
            U2 = fmaxf(U2, a2); U3 = fmaxf(U3, a3);
        }
        __syncthreads();
    }

    float um = fmax3(fmaxf(U0, U1), U2, U3);
#pragma unroll
    for (int o = 16; o; o >>= 1) um = fmaxf(um, __shfl_xor_sync(~0u, um, o));

    float* hp = g_h + (b * NN + i) * DD + d0;
    float h0 = fmaxf(hp[0], U0 - um), h1 = fmaxf(hp[1], U1 - um);
    float h2 = fmaxf(hp[2], U2 - um), h3 = fmaxf(hp[3], U3 - um);
    hp[0] = h0; hp[1] = h1; hp[2] = h2; hp[3] = h3;
    float v = fmax3(fmaxf(h0, h1), h2, h3);
#pragma unroll
    for (int o = 16; o; o >>= 1) v = fmaxf(v, __shfl_xor_sync(~0u, v, o));
    if (lane == 0) {
        int m = b * NN + i;
        g_mx2[2 * m] = v;
        g_mx2[2 * m + 1] = v;
    }
}

// ---------------------------------------------------------------
// ff1: t = max(trop_mm(h, f1W) - mx, tau) ; grid (98, 4 colsets), NT=2
// ---------------------------------------------------------------
__global__ void __launch_bounds__(256) ff1_kernel(
        const float* __restrict__ W, const float* __restrict__ tau) {
    extern __shared__ float dyn[];
    int m0 = blockIdx.x * 8, cs = blockIdx.y;
    float tv = tau[0];
    XRowT<DD> xl{g_h, m0, 784};
    trop_drive<128, 2>(xl, W + cs * 64 * DD, dyn,
        [&](int tile, float* acc, int c) {
            int mb = m0 + tile * 784;
#pragma unroll
            for (int m = 0; m < 8; m++)
                g_t[(mb + m) * DFF + cs * 64 + c] = fmaxf(acc[m] - mxv(mb + m), tv);
        });
}

// ---------------------------------------------------------------
// ff2mm: u = trop_mm(t, f2W) -> g_q scratch ; grid (196, 2), NT=1, K=256
// ---------------------------------------------------------------
__global__ void __launch_bounds__(256) ff2mm_kernel(const float* __restrict__ W) {
    extern __shared__ float dyn[];
    int m0 = blockIdx.x * 8, cs = blockIdx.y;
    XRowT<DFF> xl{g_t, m0, 0};
    trop_drive<256, 1>(xl, W + cs * 64 * DFF, dyn,
        [&](int, float* acc, int c) {
#pragma unroll
            for (int m = 0; m < 8; m++)
                g_q[(m0 + m) * DD + cs * 64 + c] = acc[m];
        });
}

// ---------------------------------------------------------------
// ff2ep: h = max(h, u - rowmax(u)); g_mx2 = rowmax(h)
// grid 196, block 128 (8 rows/block)
// ---------------------------------------------------------------
__global__ void ff2ep_kernel() {
    __shared__ float red[4][8];
    int t = threadIdx.x, m0 = blockIdx.x * 8;
    int lane = t & 31, w = t >> 5;
    float u[8], hn[8];
#pragma unroll
    for (int m = 0; m < 8; m++) {
        u[m] = g_q[(m0 + m) * DD + t];
        float v = u[m];
#pragma unroll
        for (int o = 16; o; o >>= 1) v = fmaxf(v, __shfl_xor_sync(~0u, v, o));
        if (lane == 0) red[w][m] = v;
    }
    __syncthreads();
#pragma unroll
    for (int m = 0; m < 8; m++) {
        float rm = fmax3(fmaxf(red[0][m], red[1][m]), red[2][m], red[3][m]);
        hn[m] = fmaxf(g_h[(m0 + m) * DD + t], u[m] - rm);
        g_h[(m0 + m) * DD + t] = hn[m];
    }
    __syncthreads();
#pragma unroll
    for (int m = 0; m < 8; m++) {
        float v = hn[m];
#pragma unroll
        for (int o = 16; o; o >>= 1) v = fmaxf(v, __shfl_xor_sync(~0u, v, o));
        if (lane == 0) red[w][m] = v;
    }
    __syncthreads();
    if (t < 8) {
        float v = fmax3(fmaxf(red[0][t], red[1][t]), red[2][t], red[3][t]);
        g_mx2[(m0 + t) * 2] = v;
        g_mx2[(m0 + t) * 2 + 1] = v;
    }
}

// ---------------------------------------------------------------
// head with fused tropical global pool
// grid (8, 63), block 128
// ---------------------------------------------------------------
__global__ void head_kernel(const float* __restrict__ W, const float* __restrict__ ls,
                            float* __restrict__ out) {
    __shared__ float sp[128];
    int t = threadIdx.x, b = blockIdx.x;
    const float* hp = g_h + b * NN * DD + t;
    float v0 = NEG, v1 = NEG, v2 = NEG, v3 = NEG;
    for (int n = 0; n < NN; n += 4) {
        v0 = fmaxf(v0, hp[n * DD]);
        v1 = fmaxf(v1, hp[(n + 1) * DD]);
        v2 = fmaxf(v2, hp[(n + 2) * DD]);
        v3 = fmaxf(v3, hp[(n + 3) * DD]);
    }
    sp[t] = fmax3(fmaxf(v0, v1), v2, v3);
    __syncthreads();

    int c = blockIdx.y * 16 + (t >> 3);
    int dp = (t & 7) * 16;
    float acc = NEG;
    if (c < CC) {
        const float* w = W + c * DD + dp;
#pragma unroll
        for (int d = 0; d < 16; d += 4) {
            float4 wv = *(const float4*)&w[d];
            acc = fmax3(acc, fmaxf(sp[dp + d] + wv.x, sp[dp + d + 1] + wv.y),
                        fmaxf(sp[dp + d + 2] + wv.z, sp[dp + d + 3] + wv.w));
        }
    }
#pragma unroll
    for (int o = 4; o; o >>= 1) acc = fmaxf(acc, __shfl_xor_sync(~0u, acc, o));
    if ((t & 7) == 0 && c < CC) out[b * CC + c] = acc * ls[0];
}

// ---------------------------------------------------------------
extern "C" void kernel_launch(void* const* d_in, const int* in_sizes, int n_in,
                              void* d_out, int out_size) {
    const float* x      = (const float*)d_in[0];
    const float* embedW = (const float*)d_in[1];
    const float* pos    = (const float*)d_in[2];
    const float* qW[2]  = {(const float*)d_in[3],  (const float*)d_in[9]};
    const float* kW[2]  = {(const float*)d_in[4],  (const float*)d_in[10]};
    const float* vW[2]  = {(const float*)d_in[5],  (const float*)d_in[11]};
    const float* f1W[2] = {(const float*)d_in[6],  (const float*)d_in[12]};
    const float* f2W[2] = {(const float*)d_in[7],  (const float*)d_in[13]};
    const float* tau[2] = {(const float*)d_in[8],  (const float*)d_in[14]};
    const float* headW  = (const float*)d_in[15];
    const float* ls     = (const float*)d_in[16];
    float* out = (float*)d_out;

    cudaFuncSetAttribute(embed_kernel, cudaFuncAttributeMaxDynamicSharedMemorySize, DSMEM);
    cudaFuncSetAttribute(qkv_kernel,   cudaFuncAttributeMaxDynamicSharedMemorySize, DSMEM);
    cudaFuncSetAttribute(ff1_kernel,   cudaFuncAttributeMaxDynamicSharedMemorySize, DSMEM);
    cudaFuncSetAttribute(ff2mm_kernel, cudaFuncAttributeMaxDynamicSharedMemorySize, DSMEM);

    embed_kernel<<<dim3(196, 2), 256, DSMEM>>>(x, embedW, pos);

    for (int l = 0; l < 2; l++) {
        qkv_kernel<<<dim3(98, 2, 3), 256, DSMEM>>>(qW[l], kW[l], vW[l]);
        attn_kernel<<<dim3(49, BB), 128>>>();
        ff1_kernel<<<dim3(98, 4), 256, DSMEM>>>(f1W[l], tau[l]);
        ff2mm_kernel<<<dim3(196, 2), 256, DSMEM>>>(f2W[l]);
        ff2ep_kernel<<<196, 128>>>();
    }

    head_kernel<<<dim3(BB, 63), 128>>>(headW, ls, out);
}